// round 16
// baseline (speedup 1.0000x reference)
#include <cuda_runtime.h>
#include <cuda_bf16.h>
#include <cuda_fp16.h>
#include <math.h>
#include <stdint.h>

#define E_DIM 768
#define H_NUM 12
#define D_DIM 64
#define B_NUM 4
#define S_LEN 2048
#define M_ROWS (B_NUM * S_LEN)   // 8192
#define ME (M_ROWS * E_DIM)      // 6291456
#define WE (E_DIM * E_DIM)       // 589824

// Scratch (static device globals: allocation-free)
__device__ __align__(16) __half g_Xh[3ll * ME];                      // q,k,v half
__device__ __align__(16) __half g_Wt[4ll * WE];                      // W transposed [n][k] half
__device__ __align__(16) __half g_Qh[B_NUM * H_NUM * S_LEN * D_DIM]; // [B,H,S,D]
__device__ __align__(16) __half g_Kh[B_NUM * H_NUM * S_LEN * D_DIM];
__device__ __align__(16) __half g_Vh[B_NUM * H_NUM * S_LEN * D_DIM];
__device__ __align__(16) __half g_ctx[ME];                           // [B,S,E] half

// ---------------------------------------------------------------------------
// helpers
// ---------------------------------------------------------------------------
__device__ __forceinline__ void mma_f16(float* d, uint32_t a0, uint32_t a1,
                                        uint32_t a2, uint32_t a3, uint32_t b0,
                                        uint32_t b1) {
    asm volatile(
        "mma.sync.aligned.m16n8k16.row.col.f32.f16.f16.f32 "
        "{%0,%1,%2,%3}, {%4,%5,%6,%7}, {%8,%9}, {%0,%1,%2,%3};\n"
        : "+f"(d[0]), "+f"(d[1]), "+f"(d[2]), "+f"(d[3])
        : "r"(a0), "r"(a1), "r"(a2), "r"(a3), "r"(b0), "r"(b1));
}

__device__ __forceinline__ void ldsm_x4(uint32_t& r0, uint32_t& r1,
                                        uint32_t& r2, uint32_t& r3,
                                        uint32_t addr) {
    asm volatile(
        "ldmatrix.sync.aligned.m8n8.x4.shared.b16 {%0,%1,%2,%3}, [%4];"
        : "=r"(r0), "=r"(r1), "=r"(r2), "=r"(r3) : "r"(addr));
}

__device__ __forceinline__ void ldsm_x4_t(uint32_t& r0, uint32_t& r1,
                                          uint32_t& r2, uint32_t& r3,
                                          uint32_t addr) {
    asm volatile(
        "ldmatrix.sync.aligned.m8n8.x4.trans.shared.b16 {%0,%1,%2,%3}, [%4];"
        : "=r"(r0), "=r"(r1), "=r"(r2), "=r"(r3) : "r"(addr));
}

__device__ __forceinline__ float ex2(float x) {
    float y;
    asm("ex2.approx.ftz.f32 %0, %1;" : "=f"(y) : "f"(x));
    return y;
}

__device__ __forceinline__ uint32_t pack_h2(float lo, float hi) {
    __half2 h = __floats2half2_rn(lo, hi);
    return *(uint32_t*)&h;
}

__device__ __forceinline__ void cp16(uint32_t dst_smem, const void* src) {
    asm volatile("cp.async.ca.shared.global [%0], [%1], 16;\n"
                 :: "r"(dst_smem), "l"(src));
}
#define CP_COMMIT() asm volatile("cp.async.commit_group;\n")
#define CP_WAIT2()  asm volatile("cp.async.wait_group 2;\n")
#define CP_WAIT1()  asm volatile("cp.async.wait_group 1;\n")
#define CP_WAIT0()  asm volatile("cp.async.wait_group 0;\n")

// ---------------------------------------------------------------------------
// Convert kernels
// ---------------------------------------------------------------------------
__global__ __launch_bounds__(256) void cvt_x(const float* __restrict__ q,
                                             const float* __restrict__ k,
                                             const float* __restrict__ v) {
    const int z = blockIdx.y;
    const float* X = (z == 0) ? q : (z == 1) ? k : v;
    __half* o = g_Xh + (long)z * ME;
    const long i = ((long)blockIdx.x * 256 + threadIdx.x) * 4;
    float4 f = *(const float4*)&X[i];
    uint2 u;
    u.x = pack_h2(f.x, f.y);
    u.y = pack_h2(f.z, f.w);
    *(uint2*)&o[i] = u;
}

__global__ __launch_bounds__(256) void cvt_wt(const float* __restrict__ Wq,
                                              const float* __restrict__ Wk,
                                              const float* __restrict__ Wv,
                                              const float* __restrict__ Wo) {
    __shared__ float t[32][33];
    const int z = blockIdx.z;
    const float* W = (z == 0) ? Wq : (z == 1) ? Wk : (z == 2) ? Wv : Wo;
    __half* Wt = g_Wt + (long)z * WE;
    const int tx = threadIdx.x, ty = threadIdx.y;
    const int kb = blockIdx.x * 32, nb = blockIdx.y * 32;
#pragma unroll
    for (int i = 0; i < 4; i++)
        t[ty + i * 8][tx] = W[(long)(kb + ty + i * 8) * E_DIM + nb + tx];
    __syncthreads();
#pragma unroll
    for (int i = 0; i < 4; i++)
        Wt[(long)(nb + ty + i * 8) * E_DIM + kb + tx] =
            __float2half(t[tx][ty + i * 8]);
}

// ---------------------------------------------------------------------------
// fp16 tensor-core GEMM, cp.async 3-stage pipelined, ldmatrix.x4 frag loads.
// Block tile 128x128, BK=32, 256 threads (8 warps 2x4 -> warp tile 32x64).
// ---------------------------------------------------------------------------
#define BK16 32
#define LDH 40                        // halves
#define A_HALVES (128 * LDH)          // 5120
#define STG_HALVES (2 * A_HALVES)     // 10240 halves = 20480 B per stage
#define GEMM_SMEM (3 * STG_HALVES * 2)  // 61440 B

__device__ __forceinline__ void g16_issue(uint32_t sbase, const __half* __restrict__ X,
                                          const __half* __restrict__ Wt, int m0,
                                          int n0, int k0, int tid) {
#pragma unroll
    for (int half_sel = 0; half_sel < 2; half_sel++) {
        const int ch = tid + half_sel * 256;
        const int r = ch >> 2, o = (ch & 3) * 8;  // o in halves
        cp16(sbase + (uint32_t)(r * LDH + o) * 2,
             X + (long)(m0 + r) * E_DIM + k0 + o);
        cp16(sbase + (uint32_t)(A_HALVES + r * LDH + o) * 2,
             Wt + (long)(n0 + r) * E_DIM + k0 + o);
    }
}

template <bool HEADS_OUT>
__global__ __launch_bounds__(256) void gemm_f16(
    const __half* __restrict__ Abase, const __half* __restrict__ Wtbase,
    const float* __restrict__ bias0, const float* __restrict__ bias1,
    const float* __restrict__ bias2, void* __restrict__ out0v,
    void* __restrict__ out1v, void* __restrict__ out2v) {
    extern __shared__ __half gsm[];

    const int z = blockIdx.z;
    const __half* X = Abase + (long)z * ME;
    const __half* Wt = Wtbase + (long)z * WE;
    const float* bias = (z == 0) ? bias0 : (z == 1) ? bias1 : bias2;
    void* outv = (z == 0) ? out0v : (z == 1) ? out1v : out2v;

    const int tid = threadIdx.x;
    const int w = tid >> 5, lane = tid & 31;
    const int wm = w >> 1, wn = w & 1;
    const int g = lane >> 2, c = lane & 3;
    const int m0 = blockIdx.y * 128, n0 = blockIdx.x * 128;

    const uint32_t sbase = (uint32_t)__cvta_generic_to_shared(gsm);

    const int arow_l = (lane & 7) + ((lane >> 3) & 1) * 8;
    const int acol_l = (lane >> 4) * 8;
    const int brow_l = (lane & 7) + (lane >> 4) * 8;
    const int bcol_l = ((lane >> 3) & 1) * 8;

    float acc[2][8][4];
#pragma unroll
    for (int mt = 0; mt < 2; mt++)
#pragma unroll
        for (int nt = 0; nt < 8; nt++)
#pragma unroll
            for (int j = 0; j < 4; j++) acc[mt][nt][j] = 0.0f;

    const int NT = E_DIM / BK16;  // 24
    g16_issue(sbase, X, Wt, m0, n0, 0, tid);
    CP_COMMIT();
    g16_issue(sbase + (uint32_t)(STG_HALVES * 2), X, Wt, m0, n0, BK16, tid);
    CP_COMMIT();

    int cs = 0, is = 2;
    for (int t = 0; t < NT; t++) {
        if (t + 2 < NT) {
            g16_issue(sbase + (uint32_t)(is * STG_HALVES * 2), X, Wt, m0, n0,
                      (t + 2) * BK16, tid);
            CP_COMMIT();
            is = (is == 2) ? 0 : is + 1;
            CP_WAIT2();
        } else if (t + 1 < NT) {
            CP_WAIT1();
        } else {
            CP_WAIT0();
        }
        __syncthreads();

        const uint32_t as_b = sbase + (uint32_t)(cs * STG_HALVES * 2);
        const uint32_t bs_b = as_b + (uint32_t)(A_HALVES * 2);
        cs = (cs == 2) ? 0 : cs + 1;

#pragma unroll
        for (int ks = 0; ks < 2; ks++) {
            uint32_t a[2][4];
#pragma unroll
            for (int mt = 0; mt < 2; mt++)
                ldsm_x4(a[mt][0], a[mt][1], a[mt][2], a[mt][3],
                        as_b + (uint32_t)(((wm * 32 + mt * 16 + arow_l) * LDH +
                                           ks * 16 + acol_l) * 2));
#pragma unroll
            for (int ntp = 0; ntp < 4; ntp++) {
                uint32_t b0, b1, b2, b3;
                ldsm_x4(b0, b1, b2, b3,
                        bs_b + (uint32_t)(((wn * 64 + ntp * 16 + brow_l) * LDH +
                                           ks * 16 + bcol_l) * 2));
                mma_f16(acc[0][2 * ntp], a[0][0], a[0][1], a[0][2], a[0][3], b0, b1);
                mma_f16(acc[1][2 * ntp], a[1][0], a[1][1], a[1][2], a[1][3], b0, b1);
                mma_f16(acc[0][2 * ntp + 1], a[0][0], a[0][1], a[0][2], a[0][3], b2, b3);
                mma_f16(acc[1][2 * ntp + 1], a[1][0], a[1][1], a[1][2], a[1][3], b2, b3);
            }
        }
        __syncthreads();
    }

    // Epilogue
#pragma unroll
    for (int mt = 0; mt < 2; mt++) {
        const int r0 = m0 + wm * 32 + mt * 16 + g;
#pragma unroll
        for (int nt = 0; nt < 8; nt++) {
            const int col = n0 + wn * 64 + nt * 8 + 2 * c;
            const float bb0 = bias[col], bb1 = bias[col + 1];
            const float v00 = acc[mt][nt][0] + bb0;
            const float v01 = acc[mt][nt][1] + bb1;
            const float v10 = acc[mt][nt][2] + bb0;
            const float v11 = acc[mt][nt][3] + bb1;
            if (HEADS_OUT) {
                __half* out = (__half*)outv;
                const int hh = col >> 6, d = col & 63;
                const int b0i = r0 >> 11, s0 = r0 & 2047;
                const int r1 = r0 + 8;
                const int b1i = r1 >> 11, s1 = r1 & 2047;
                *(uint32_t*)&out[((long)(b0i * H_NUM + hh) * S_LEN + s0) * D_DIM + d] =
                    pack_h2(v00, v01);
                *(uint32_t*)&out[((long)(b1i * H_NUM + hh) * S_LEN + s1) * D_DIM + d] =
                    pack_h2(v10, v11);
            } else {
                float* out = (float*)outv;
                *(float2*)&out[(long)r0 * E_DIM + col] = make_float2(v00, v01);
                *(float2*)&out[(long)(r0 + 8) * E_DIM + col] = make_float2(v10, v11);
            }
        }
    }
}

// ---------------------------------------------------------------------------
// fp16 flash attention. Br=128 (8 warps, 256 thr), Bc=64, D=64, half in/out.
// cp.async double-buffered K/V; mask handled via per-block ballot bitmask
// (2 broadcast LDS + ALU per tile instead of 16 scalar LDS per warp).
// ---------------------------------------------------------------------------
#define SCALE2 (0.125f * 1.44269504088896f)  // 1/sqrt(64) * log2(e)
#define KST 72
#define TILE_HALVES (64 * KST)   // 4608
#define NBIG 1.442695e9f

__global__ __launch_bounds__(256) void attn_f16(const int* __restrict__ mask,
                                                const __half* __restrict__ Qh,
                                                const __half* __restrict__ Kh,
                                                const __half* __restrict__ Vh,
                                                __half* __restrict__ ctx) {
    __shared__ __half KVs[2][2][TILE_HALVES];  // [stage][K=0/V=1]
    __shared__ uint32_t mbits[64];             // 2048-key mask bitset

    const int b = blockIdx.z, h = blockIdx.y;
    const int q0 = blockIdx.x * 128;
    const int tid = threadIdx.x;
    const int lane = tid & 31, w = tid >> 5;   // 8 warps
    const int g = lane >> 2, c = lane & 3;

    const long base = (long)(b * H_NUM + h) * S_LEN * D_DIM;
    const __half* Q = Qh + base;
    const __half* K = Kh + base;
    const __half* V = Vh + base;
    const int* mrow = mask + b * S_LEN;

    const uint32_t kv_sb = (uint32_t)__cvta_generic_to_shared(&KVs[0][0][0]);

    // build mask bitset: warp w handles words w*8..w*8+7 (once per block)
#pragma unroll
    for (int j = 0; j < 8; j++) {
        const int word = w * 8 + j;
        const uint32_t bal =
            __ballot_sync(0xffffffffu, mrow[word * 32 + lane] != 0);
        if (lane == 0) mbits[word] = bal;
    }

    // ldmatrix per-lane address components
    const int krow_l = (lane & 7) + (lane >> 4) * 8;
    const int kcol_l = ((lane >> 3) & 1) * 8;
    const int vrow_l = lane & 15;
    const int vsel_l = lane >> 4;

    // Q A-fragments (pre-scaled, fp16)
    uint32_t aq[4][4];
    {
        const __half* q_r0 = Q + (long)(q0 + w * 16 + g) * D_DIM;
        const __half* q_r1 = q_r0 + 8 * D_DIM;
#pragma unroll
        for (int ks = 0; ks < 4; ks++) {
            float2 p0 = __half22float2(*(const __half2*)&q_r0[ks * 16 + 2 * c]);
            float2 p1 = __half22float2(*(const __half2*)&q_r1[ks * 16 + 2 * c]);
            float2 p2 = __half22float2(*(const __half2*)&q_r0[ks * 16 + 2 * c + 8]);
            float2 p3 = __half22float2(*(const __half2*)&q_r1[ks * 16 + 2 * c + 8]);
            aq[ks][0] = pack_h2(p0.x * SCALE2, p0.y * SCALE2);
            aq[ks][1] = pack_h2(p1.x * SCALE2, p1.y * SCALE2);
            aq[ks][2] = pack_h2(p2.x * SCALE2, p2.y * SCALE2);
            aq[ks][3] = pack_h2(p3.x * SCALE2, p3.y * SCALE2);
        }
    }

    float O[8][4];
#pragma unroll
    for (int nt = 0; nt < 8; nt++)
#pragma unroll
        for (int j = 0; j < 4; j++) O[nt][j] = 0.0f;
    float mm0 = -1e30f, mm1 = -1e30f, l0 = 0.0f, l1 = 0.0f;

    // K/V tile issue: 512 16B-chunks each, 256 threads x 2
    auto issue_tile = [&](int kt, int st) {
        const int k0 = kt * 64;
        const uint32_t kb = kv_sb + (uint32_t)((st * 2) * TILE_HALVES * 2);
        const uint32_t vb = kb + (uint32_t)(TILE_HALVES * 2);
#pragma unroll
        for (int i = 0; i < 2; i++) {
            const int ch = i * 256 + tid;
            const int r = ch >> 3, o = (ch & 7) * 8;
            cp16(kb + (uint32_t)(r * KST + o) * 2, K + (long)(k0 + r) * D_DIM + o);
            cp16(vb + (uint32_t)(r * KST + o) * 2, V + (long)(k0 + r) * D_DIM + o);
        }
    };

    issue_tile(0, 0);
    CP_COMMIT();

    const int NTILES = S_LEN / 64;  // 32
    for (int t = 0; t < NTILES; t++) {
        if (t + 1 < NTILES) {
            issue_tile(t + 1, (t + 1) & 1);
            CP_COMMIT();
            CP_WAIT1();
        } else {
            CP_WAIT0();
        }
        __syncthreads();

        const int st = t & 1;
        const uint32_t ks_addr = kv_sb + (uint32_t)((st * 2) * TILE_HALVES * 2);
        const uint32_t vs_addr = ks_addr + (uint32_t)(TILE_HALVES * 2);
        const uint32_t mw0 = mbits[2 * t], mw1 = mbits[2 * t + 1];

        // S = (Q*scale) K^T  — K frags via ldmatrix.x4
        float S[8][4];
#pragma unroll
        for (int nt = 0; nt < 8; nt++)
#pragma unroll
            for (int j = 0; j < 4; j++) S[nt][j] = 0.0f;

#pragma unroll
        for (int ks = 0; ks < 4; ks++) {
#pragma unroll
            for (int ntp = 0; ntp < 4; ntp++) {
                uint32_t b0, b1, b2, b3;
                ldsm_x4(b0, b1, b2, b3,
                        ks_addr + (uint32_t)(((ntp * 16 + krow_l) * KST +
                                              ks * 16 + kcol_l) * 2));
                mma_f16(S[2 * ntp], aq[ks][0], aq[ks][1], aq[ks][2], aq[ks][3], b0, b1);
                mma_f16(S[2 * ntp + 1], aq[ks][0], aq[ks][1], aq[ks][2], aq[ks][3], b2, b3);
            }
        }

        // mask bias from bitset + online softmax
        float mx0 = -1e30f, mx1 = -1e30f;
#pragma unroll
        for (int nt = 0; nt < 8; nt++) {
            const uint32_t word = (nt < 4) ? mw0 : mw1;
            const uint32_t v2 = word >> ((nt & 3) * 8 + 2 * c);
            const float bb0 = (v2 & 1u) ? 0.0f : -NBIG;
            const float bb1 = (v2 & 2u) ? 0.0f : -NBIG;
            S[nt][0] += bb0;
            S[nt][1] += bb1;
            S[nt][2] += bb0;
            S[nt][3] += bb1;
            mx0 = fmaxf(mx0, fmaxf(S[nt][0], S[nt][1]));
            mx1 = fmaxf(mx1, fmaxf(S[nt][2], S[nt][3]));
        }
        mx0 = fmaxf(mx0, __shfl_xor_sync(0xffffffffu, mx0, 1));
        mx0 = fmaxf(mx0, __shfl_xor_sync(0xffffffffu, mx0, 2));
        mx1 = fmaxf(mx1, __shfl_xor_sync(0xffffffffu, mx1, 1));
        mx1 = fmaxf(mx1, __shfl_xor_sync(0xffffffffu, mx1, 2));

        const float M0 = fmaxf(mm0, mx0), M1 = fmaxf(mm1, mx1);
        const float a0 = ex2(mm0 - M0), a1 = ex2(mm1 - M1);
        mm0 = M0;
        mm1 = M1;

        float s0 = 0.0f, s1 = 0.0f;
        uint32_t Pp[8][2];
#pragma unroll
        for (int nt = 0; nt < 8; nt++) {
            S[nt][0] = ex2(S[nt][0] - M0);
            S[nt][1] = ex2(S[nt][1] - M0);
            S[nt][2] = ex2(S[nt][2] - M1);
            S[nt][3] = ex2(S[nt][3] - M1);
            s0 += S[nt][0] + S[nt][1];
            s1 += S[nt][2] + S[nt][3];
            Pp[nt][0] = pack_h2(S[nt][0], S[nt][1]);
            Pp[nt][1] = pack_h2(S[nt][2], S[nt][3]);
        }
        s0 += __shfl_xor_sync(0xffffffffu, s0, 1);
        s0 += __shfl_xor_sync(0xffffffffu, s0, 2);
        s1 += __shfl_xor_sync(0xffffffffu, s1, 1);
        s1 += __shfl_xor_sync(0xffffffffu, s1, 2);
        l0 = l0 * a0 + s0;
        l1 = l1 * a1 + s1;

#pragma unroll
        for (int nt = 0; nt < 8; nt++) {
            O[nt][0] *= a0;
            O[nt][1] *= a0;
            O[nt][2] *= a1;
            O[nt][3] *= a1;
        }

        // O += P @ V ; V frags via ldmatrix.x4.trans
#pragma unroll
        for (int ks = 0; ks < 4; ks++) {
            const uint32_t rowa =
                vs_addr + (uint32_t)(((ks * 16 + vrow_l) * KST) * 2);
#pragma unroll
            for (int ntp = 0; ntp < 4; ntp++) {
                uint32_t b0, b1, b2, b3;
                ldsm_x4_t(b0, b1, b2, b3,
                          rowa + (uint32_t)((ntp * 2 + vsel_l) * 16));
                mma_f16(O[2 * ntp], Pp[2 * ks][0], Pp[2 * ks][1],
                        Pp[2 * ks + 1][0], Pp[2 * ks + 1][1], b0, b1);
                mma_f16(O[2 * ntp + 1], Pp[2 * ks][0], Pp[2 * ks][1],
                        Pp[2 * ks + 1][0], Pp[2 * ks + 1][1], b2, b3);
            }
        }
        __syncthreads();
    }

    // epilogue: ctx half
    const float inv0 = 1.0f / l0, inv1 = 1.0f / l1;
    const int r0 = q0 + w * 16 + g;
#pragma unroll
    for (int nt = 0; nt < 8; nt++) {
        const int col = h * D_DIM + nt * 8 + 2 * c;
        *(uint32_t*)&ctx[((long)b * S_LEN + r0) * E_DIM + col] =
            pack_h2(O[nt][0] * inv0, O[nt][1] * inv0);
        *(uint32_t*)&ctx[((long)b * S_LEN + r0 + 8) * E_DIM + col] =
            pack_h2(O[nt][2] * inv1, O[nt][3] * inv1);
    }
}

// ---------------------------------------------------------------------------
extern "C" void kernel_launch(void* const* d_in, const int* in_sizes, int n_in,
                              void* d_out, int out_size) {
    const float* q = (const float*)d_in[0];
    const float* k = (const float*)d_in[1];
    const float* v = (const float*)d_in[2];
    const int* mask = (const int*)d_in[3];
    const float* Wq = (const float*)d_in[4];
    const float* bq = (const float*)d_in[5];
    const float* Wk = (const float*)d_in[6];
    const float* bk = (const float*)d_in[7];
    const float* Wv = (const float*)d_in[8];
    const float* bv = (const float*)d_in[9];
    const float* Wo = (const float*)d_in[10];
    const float* bo = (const float*)d_in[11];

    __half *Xh, *Wt, *Qh, *Kh, *Vh, *Ctx;
    cudaGetSymbolAddress((void**)&Xh, g_Xh);
    cudaGetSymbolAddress((void**)&Wt, g_Wt);
    cudaGetSymbolAddress((void**)&Qh, g_Qh);
    cudaGetSymbolAddress((void**)&Kh, g_Kh);
    cudaGetSymbolAddress((void**)&Vh, g_Vh);
    cudaGetSymbolAddress((void**)&Ctx, g_ctx);

    cudaFuncSetAttribute(gemm_f16<true>,
                         cudaFuncAttributeMaxDynamicSharedMemorySize, GEMM_SMEM);
    cudaFuncSetAttribute(gemm_f16<false>,
                         cudaFuncAttributeMaxDynamicSharedMemorySize, GEMM_SMEM);

    // converts
    cvt_x<<<dim3(ME / 1024, 3), 256>>>(q, k, v);
    cvt_wt<<<dim3(24, 24, 4), dim3(32, 8)>>>(Wq, Wk, Wv, Wo);

    // merged Q/K/V projections
    gemm_f16<true><<<dim3(6, 64, 3), 256, GEMM_SMEM>>>(Xh, Wt, bq, bk, bv, Qh,
                                                       Kh, Vh);

    attn_f16<<<dim3(S_LEN / 128, H_NUM, B_NUM), 256>>>(mask, Qh, Kh, Vh, Ctx);

    gemm_f16<false><<<dim3(6, 64, 1), 256, GEMM_SMEM>>>(
        Ctx, Wt + 3ll * WE, bo, bo, bo, d_out, d_out, d_out);
}

// round 17
// speedup vs baseline: 1.0356x; 1.0356x over previous
#include <cuda_runtime.h>
#include <cuda_bf16.h>
#include <cuda_fp16.h>
#include <math.h>
#include <stdint.h>

#define E_DIM 768
#define H_NUM 12
#define D_DIM 64
#define B_NUM 4
#define S_LEN 2048
#define M_ROWS (B_NUM * S_LEN)   // 8192
#define ME (M_ROWS * E_DIM)      // 6291456
#define WE (E_DIM * E_DIM)       // 589824

// Scratch (static device globals: allocation-free)
__device__ __align__(16) __half g_Xh[3ll * ME];                      // q,k,v half
__device__ __align__(16) __half g_Wt[4ll * WE];                      // W transposed [n][k] half
__device__ __align__(16) __half g_Qh[B_NUM * H_NUM * S_LEN * D_DIM]; // [B,H,S,D]
__device__ __align__(16) __half g_Kh[B_NUM * H_NUM * S_LEN * D_DIM];
__device__ __align__(16) __half g_Vh[B_NUM * H_NUM * S_LEN * D_DIM];
__device__ __align__(16) __half g_ctx[ME];                           // [B,S,E] half

// ---------------------------------------------------------------------------
// helpers
// ---------------------------------------------------------------------------
__device__ __forceinline__ void mma_f16(float* d, uint32_t a0, uint32_t a1,
                                        uint32_t a2, uint32_t a3, uint32_t b0,
                                        uint32_t b1) {
    asm volatile(
        "mma.sync.aligned.m16n8k16.row.col.f32.f16.f16.f32 "
        "{%0,%1,%2,%3}, {%4,%5,%6,%7}, {%8,%9}, {%0,%1,%2,%3};\n"
        : "+f"(d[0]), "+f"(d[1]), "+f"(d[2]), "+f"(d[3])
        : "r"(a0), "r"(a1), "r"(a2), "r"(a3), "r"(b0), "r"(b1));
}

__device__ __forceinline__ void ldsm_x4(uint32_t& r0, uint32_t& r1,
                                        uint32_t& r2, uint32_t& r3,
                                        uint32_t addr) {
    asm volatile(
        "ldmatrix.sync.aligned.m8n8.x4.shared.b16 {%0,%1,%2,%3}, [%4];"
        : "=r"(r0), "=r"(r1), "=r"(r2), "=r"(r3) : "r"(addr));
}

__device__ __forceinline__ void ldsm_x4_t(uint32_t& r0, uint32_t& r1,
                                          uint32_t& r2, uint32_t& r3,
                                          uint32_t addr) {
    asm volatile(
        "ldmatrix.sync.aligned.m8n8.x4.trans.shared.b16 {%0,%1,%2,%3}, [%4];"
        : "=r"(r0), "=r"(r1), "=r"(r2), "=r"(r3) : "r"(addr));
}

__device__ __forceinline__ float ex2(float x) {
    float y;
    asm("ex2.approx.ftz.f32 %0, %1;" : "=f"(y) : "f"(x));
    return y;
}

__device__ __forceinline__ uint32_t pack_h2(float lo, float hi) {
    __half2 h = __floats2half2_rn(lo, hi);
    return *(uint32_t*)&h;
}

__device__ __forceinline__ void cp16(uint32_t dst_smem, const void* src) {
    asm volatile("cp.async.ca.shared.global [%0], [%1], 16;\n"
                 :: "r"(dst_smem), "l"(src));
}
#define CP_COMMIT() asm volatile("cp.async.commit_group;\n")
#define CP_WAIT2()  asm volatile("cp.async.wait_group 2;\n")
#define CP_WAIT1()  asm volatile("cp.async.wait_group 1;\n")
#define CP_WAIT0()  asm volatile("cp.async.wait_group 0;\n")

// ---------------------------------------------------------------------------
// Convert kernels
// ---------------------------------------------------------------------------
__global__ __launch_bounds__(256) void cvt_x(const float* __restrict__ q,
                                             const float* __restrict__ k,
                                             const float* __restrict__ v) {
    const int z = blockIdx.y;
    const float* X = (z == 0) ? q : (z == 1) ? k : v;
    __half* o = g_Xh + (long)z * ME;
    const long i = ((long)blockIdx.x * 256 + threadIdx.x) * 4;
    float4 f = *(const float4*)&X[i];
    uint2 u;
    u.x = pack_h2(f.x, f.y);
    u.y = pack_h2(f.z, f.w);
    *(uint2*)&o[i] = u;
}

__global__ __launch_bounds__(256) void cvt_wt(const float* __restrict__ Wq,
                                              const float* __restrict__ Wk,
                                              const float* __restrict__ Wv,
                                              const float* __restrict__ Wo) {
    __shared__ float t[32][33];
    const int z = blockIdx.z;
    const float* W = (z == 0) ? Wq : (z == 1) ? Wk : (z == 2) ? Wv : Wo;
    __half* Wt = g_Wt + (long)z * WE;
    const int tx = threadIdx.x, ty = threadIdx.y;
    const int kb = blockIdx.x * 32, nb = blockIdx.y * 32;
#pragma unroll
    for (int i = 0; i < 4; i++)
        t[ty + i * 8][tx] = W[(long)(kb + ty + i * 8) * E_DIM + nb + tx];
    __syncthreads();
#pragma unroll
    for (int i = 0; i < 4; i++)
        Wt[(long)(nb + ty + i * 8) * E_DIM + kb + tx] =
            __float2half(t[tx][ty + i * 8]);
}

// ---------------------------------------------------------------------------
// fp16 tensor-core GEMM, cp.async 3-stage pipelined, ldmatrix.x4 frag loads.
// Block tile 128x128, BK=32, 256 threads (8 warps 2x4 -> warp tile 32x64).
// ---------------------------------------------------------------------------
#define BK16 32
#define LDH 40                        // halves
#define A_HALVES (128 * LDH)          // 5120
#define STG_HALVES (2 * A_HALVES)     // 10240 halves = 20480 B per stage
#define GEMM_SMEM (3 * STG_HALVES * 2)  // 61440 B

__device__ __forceinline__ void g16_issue(uint32_t sbase, const __half* __restrict__ X,
                                          const __half* __restrict__ Wt, int m0,
                                          int n0, int k0, int tid) {
#pragma unroll
    for (int half_sel = 0; half_sel < 2; half_sel++) {
        const int ch = tid + half_sel * 256;
        const int r = ch >> 2, o = (ch & 3) * 8;  // o in halves
        cp16(sbase + (uint32_t)(r * LDH + o) * 2,
             X + (long)(m0 + r) * E_DIM + k0 + o);
        cp16(sbase + (uint32_t)(A_HALVES + r * LDH + o) * 2,
             Wt + (long)(n0 + r) * E_DIM + k0 + o);
    }
}

template <bool HEADS_OUT>
__global__ __launch_bounds__(256) void gemm_f16(
    const __half* __restrict__ Abase, const __half* __restrict__ Wtbase,
    const float* __restrict__ bias0, const float* __restrict__ bias1,
    const float* __restrict__ bias2, void* __restrict__ out0v,
    void* __restrict__ out1v, void* __restrict__ out2v) {
    extern __shared__ __half gsm[];

    const int z = blockIdx.z;
    const __half* X = Abase + (long)z * ME;
    const __half* Wt = Wtbase + (long)z * WE;
    const float* bias = (z == 0) ? bias0 : (z == 1) ? bias1 : bias2;
    void* outv = (z == 0) ? out0v : (z == 1) ? out1v : out2v;

    const int tid = threadIdx.x;
    const int w = tid >> 5, lane = tid & 31;
    const int wm = w >> 1, wn = w & 1;
    const int g = lane >> 2, c = lane & 3;
    const int m0 = blockIdx.y * 128, n0 = blockIdx.x * 128;

    const uint32_t sbase = (uint32_t)__cvta_generic_to_shared(gsm);

    const int arow_l = (lane & 7) + ((lane >> 3) & 1) * 8;
    const int acol_l = (lane >> 4) * 8;
    const int brow_l = (lane & 7) + (lane >> 4) * 8;
    const int bcol_l = ((lane >> 3) & 1) * 8;

    float acc[2][8][4];
#pragma unroll
    for (int mt = 0; mt < 2; mt++)
#pragma unroll
        for (int nt = 0; nt < 8; nt++)
#pragma unroll
            for (int j = 0; j < 4; j++) acc[mt][nt][j] = 0.0f;

    const int NT = E_DIM / BK16;  // 24
    g16_issue(sbase, X, Wt, m0, n0, 0, tid);
    CP_COMMIT();
    g16_issue(sbase + (uint32_t)(STG_HALVES * 2), X, Wt, m0, n0, BK16, tid);
    CP_COMMIT();

    int cs = 0, is = 2;
    for (int t = 0; t < NT; t++) {
        if (t + 2 < NT) {
            g16_issue(sbase + (uint32_t)(is * STG_HALVES * 2), X, Wt, m0, n0,
                      (t + 2) * BK16, tid);
            CP_COMMIT();
            is = (is == 2) ? 0 : is + 1;
            CP_WAIT2();
        } else if (t + 1 < NT) {
            CP_WAIT1();
        } else {
            CP_WAIT0();
        }
        __syncthreads();

        const uint32_t as_b = sbase + (uint32_t)(cs * STG_HALVES * 2);
        const uint32_t bs_b = as_b + (uint32_t)(A_HALVES * 2);
        cs = (cs == 2) ? 0 : cs + 1;

#pragma unroll
        for (int ks = 0; ks < 2; ks++) {
            uint32_t a[2][4];
#pragma unroll
            for (int mt = 0; mt < 2; mt++)
                ldsm_x4(a[mt][0], a[mt][1], a[mt][2], a[mt][3],
                        as_b + (uint32_t)(((wm * 32 + mt * 16 + arow_l) * LDH +
                                           ks * 16 + acol_l) * 2));
#pragma unroll
            for (int ntp = 0; ntp < 4; ntp++) {
                uint32_t b0, b1, b2, b3;
                ldsm_x4(b0, b1, b2, b3,
                        bs_b + (uint32_t)(((wn * 64 + ntp * 16 + brow_l) * LDH +
                                           ks * 16 + bcol_l) * 2));
                mma_f16(acc[0][2 * ntp], a[0][0], a[0][1], a[0][2], a[0][3], b0, b1);
                mma_f16(acc[1][2 * ntp], a[1][0], a[1][1], a[1][2], a[1][3], b0, b1);
                mma_f16(acc[0][2 * ntp + 1], a[0][0], a[0][1], a[0][2], a[0][3], b2, b3);
                mma_f16(acc[1][2 * ntp + 1], a[1][0], a[1][1], a[1][2], a[1][3], b2, b3);
            }
        }
        __syncthreads();
    }

    // Epilogue
#pragma unroll
    for (int mt = 0; mt < 2; mt++) {
        const int r0 = m0 + wm * 32 + mt * 16 + g;
#pragma unroll
        for (int nt = 0; nt < 8; nt++) {
            const int col = n0 + wn * 64 + nt * 8 + 2 * c;
            const float bb0 = bias[col], bb1 = bias[col + 1];
            const float v00 = acc[mt][nt][0] + bb0;
            const float v01 = acc[mt][nt][1] + bb1;
            const float v10 = acc[mt][nt][2] + bb0;
            const float v11 = acc[mt][nt][3] + bb1;
            if (HEADS_OUT) {
                __half* out = (__half*)outv;
                const int hh = col >> 6, d = col & 63;
                const int b0i = r0 >> 11, s0 = r0 & 2047;
                const int r1 = r0 + 8;
                const int b1i = r1 >> 11, s1 = r1 & 2047;
                *(uint32_t*)&out[((long)(b0i * H_NUM + hh) * S_LEN + s0) * D_DIM + d] =
                    pack_h2(v00, v01);
                *(uint32_t*)&out[((long)(b1i * H_NUM + hh) * S_LEN + s1) * D_DIM + d] =
                    pack_h2(v10, v11);
            } else {
                float* out = (float*)outv;
                *(float2*)&out[(long)r0 * E_DIM + col] = make_float2(v00, v01);
                *(float2*)&out[(long)(r0 + 8) * E_DIM + col] = make_float2(v10, v11);
            }
        }
    }
}

// ---------------------------------------------------------------------------
// fp16 flash attention. Br=64 (4 warps, 128 thr — R11 proven layout), Bc=64.
// cp.async double-buffered K/V; mask via per-block ballot bitmask
// (2 broadcast LDS + ALU per tile instead of 16 scalar LDS per warp).
// ---------------------------------------------------------------------------
#define SCALE2 (0.125f * 1.44269504088896f)  // 1/sqrt(64) * log2(e)
#define KST 72
#define TILE_HALVES (64 * KST)   // 4608
#define NBIG 1.442695e9f

__global__ __launch_bounds__(128) void attn_f16(const int* __restrict__ mask,
                                                const __half* __restrict__ Qh,
                                                const __half* __restrict__ Kh,
                                                const __half* __restrict__ Vh,
                                                __half* __restrict__ ctx) {
    __shared__ __half KVs[2][2][TILE_HALVES];  // [stage][K=0/V=1]
    __shared__ uint32_t mbits[64];             // 2048-key mask bitset

    const int b = blockIdx.z, h = blockIdx.y;
    const int q0 = blockIdx.x * 64;
    const int tid = threadIdx.x;
    const int lane = tid & 31, w = tid >> 5;   // 4 warps
    const int g = lane >> 2, c = lane & 3;

    const long base = (long)(b * H_NUM + h) * S_LEN * D_DIM;
    const __half* Q = Qh + base;
    const __half* K = Kh + base;
    const __half* V = Vh + base;
    const int* mrow = mask + b * S_LEN;

    const uint32_t kv_sb = (uint32_t)__cvta_generic_to_shared(&KVs[0][0][0]);

    // build mask bitset: warp w handles words w*16..w*16+15 (once per block)
#pragma unroll
    for (int j = 0; j < 16; j++) {
        const int word = w * 16 + j;
        const uint32_t bal =
            __ballot_sync(0xffffffffu, mrow[word * 32 + lane] != 0);
        if (lane == 0) mbits[word] = bal;
    }

    // ldmatrix per-lane address components
    const int krow_l = (lane & 7) + (lane >> 4) * 8;
    const int kcol_l = ((lane >> 3) & 1) * 8;
    const int vrow_l = lane & 15;
    const int vsel_l = lane >> 4;

    // Q A-fragments (pre-scaled, fp16)
    uint32_t aq[4][4];
    {
        const __half* q_r0 = Q + (long)(q0 + w * 16 + g) * D_DIM;
        const __half* q_r1 = q_r0 + 8 * D_DIM;
#pragma unroll
        for (int ks = 0; ks < 4; ks++) {
            float2 p0 = __half22float2(*(const __half2*)&q_r0[ks * 16 + 2 * c]);
            float2 p1 = __half22float2(*(const __half2*)&q_r1[ks * 16 + 2 * c]);
            float2 p2 = __half22float2(*(const __half2*)&q_r0[ks * 16 + 2 * c + 8]);
            float2 p3 = __half22float2(*(const __half2*)&q_r1[ks * 16 + 2 * c + 8]);
            aq[ks][0] = pack_h2(p0.x * SCALE2, p0.y * SCALE2);
            aq[ks][1] = pack_h2(p1.x * SCALE2, p1.y * SCALE2);
            aq[ks][2] = pack_h2(p2.x * SCALE2, p2.y * SCALE2);
            aq[ks][3] = pack_h2(p3.x * SCALE2, p3.y * SCALE2);
        }
    }

    float O[8][4];
#pragma unroll
    for (int nt = 0; nt < 8; nt++)
#pragma unroll
        for (int j = 0; j < 4; j++) O[nt][j] = 0.0f;
    float mm0 = -1e30f, mm1 = -1e30f, l0 = 0.0f, l1 = 0.0f;

    // K/V tile issue: 512 16B-chunks each, 128 threads x 4 (R11 proven map)
    auto issue_tile = [&](int kt, int st) {
        const int k0 = kt * 64;
        const uint32_t kb = kv_sb + (uint32_t)((st * 2) * TILE_HALVES * 2);
        const uint32_t vb = kb + (uint32_t)(TILE_HALVES * 2);
#pragma unroll
        for (int i = 0; i < 4; i++) {
            const int ch = i * 128 + tid;
            const int r = ch >> 3, o = (ch & 7) * 8;
            cp16(kb + (uint32_t)(r * KST + o) * 2, K + (long)(k0 + r) * D_DIM + o);
            cp16(vb + (uint32_t)(r * KST + o) * 2, V + (long)(k0 + r) * D_DIM + o);
        }
    };

    issue_tile(0, 0);
    CP_COMMIT();

    const int NTILES = S_LEN / 64;  // 32
    for (int t = 0; t < NTILES; t++) {
        if (t + 1 < NTILES) {
            issue_tile(t + 1, (t + 1) & 1);
            CP_COMMIT();
            CP_WAIT1();
        } else {
            CP_WAIT0();
        }
        __syncthreads();

        const int st = t & 1;
        const uint32_t ks_addr = kv_sb + (uint32_t)((st * 2) * TILE_HALVES * 2);
        const uint32_t vs_addr = ks_addr + (uint32_t)(TILE_HALVES * 2);
        const uint32_t mw0 = mbits[2 * t], mw1 = mbits[2 * t + 1];

        // S = (Q*scale) K^T  — K frags via ldmatrix.x4
        float S[8][4];
#pragma unroll
        for (int nt = 0; nt < 8; nt++)
#pragma unroll
            for (int j = 0; j < 4; j++) S[nt][j] = 0.0f;

#pragma unroll
        for (int ks = 0; ks < 4; ks++) {
#pragma unroll
            for (int ntp = 0; ntp < 4; ntp++) {
                uint32_t b0, b1, b2, b3;
                ldsm_x4(b0, b1, b2, b3,
                        ks_addr + (uint32_t)(((ntp * 16 + krow_l) * KST +
                                              ks * 16 + kcol_l) * 2));
                mma_f16(S[2 * ntp], aq[ks][0], aq[ks][1], aq[ks][2], aq[ks][3], b0, b1);
                mma_f16(S[2 * ntp + 1], aq[ks][0], aq[ks][1], aq[ks][2], aq[ks][3], b2, b3);
            }
        }

        // mask bias from bitset + online softmax
        float mx0 = -1e30f, mx1 = -1e30f;
#pragma unroll
        for (int nt = 0; nt < 8; nt++) {
            const uint32_t word = (nt < 4) ? mw0 : mw1;
            const uint32_t v2 = word >> ((nt & 3) * 8 + 2 * c);
            const float bb0 = (v2 & 1u) ? 0.0f : -NBIG;
            const float bb1 = (v2 & 2u) ? 0.0f : -NBIG;
            S[nt][0] += bb0;
            S[nt][1] += bb1;
            S[nt][2] += bb0;
            S[nt][3] += bb1;
            mx0 = fmaxf(mx0, fmaxf(S[nt][0], S[nt][1]));
            mx1 = fmaxf(mx1, fmaxf(S[nt][2], S[nt][3]));
        }
        mx0 = fmaxf(mx0, __shfl_xor_sync(0xffffffffu, mx0, 1));
        mx0 = fmaxf(mx0, __shfl_xor_sync(0xffffffffu, mx0, 2));
        mx1 = fmaxf(mx1, __shfl_xor_sync(0xffffffffu, mx1, 1));
        mx1 = fmaxf(mx1, __shfl_xor_sync(0xffffffffu, mx1, 2));

        const float M0 = fmaxf(mm0, mx0), M1 = fmaxf(mm1, mx1);
        const float a0 = ex2(mm0 - M0), a1 = ex2(mm1 - M1);
        mm0 = M0;
        mm1 = M1;

        float s0 = 0.0f, s1 = 0.0f;
        uint32_t Pp[8][2];
#pragma unroll
        for (int nt = 0; nt < 8; nt++) {
            S[nt][0] = ex2(S[nt][0] - M0);
            S[nt][1] = ex2(S[nt][1] - M0);
            S[nt][2] = ex2(S[nt][2] - M1);
            S[nt][3] = ex2(S[nt][3] - M1);
            s0 += S[nt][0] + S[nt][1];
            s1 += S[nt][2] + S[nt][3];
            Pp[nt][0] = pack_h2(S[nt][0], S[nt][1]);
            Pp[nt][1] = pack_h2(S[nt][2], S[nt][3]);
        }
        s0 += __shfl_xor_sync(0xffffffffu, s0, 1);
        s0 += __shfl_xor_sync(0xffffffffu, s0, 2);
        s1 += __shfl_xor_sync(0xffffffffu, s1, 1);
        s1 += __shfl_xor_sync(0xffffffffu, s1, 2);
        l0 = l0 * a0 + s0;
        l1 = l1 * a1 + s1;

#pragma unroll
        for (int nt = 0; nt < 8; nt++) {
            O[nt][0] *= a0;
            O[nt][1] *= a0;
            O[nt][2] *= a1;
            O[nt][3] *= a1;
        }

        // O += P @ V ; V frags via ldmatrix.x4.trans
#pragma unroll
        for (int ks = 0; ks < 4; ks++) {
            const uint32_t rowa =
                vs_addr + (uint32_t)(((ks * 16 + vrow_l) * KST) * 2);
#pragma unroll
            for (int ntp = 0; ntp < 4; ntp++) {
                uint32_t b0, b1, b2, b3;
                ldsm_x4_t(b0, b1, b2, b3,
                          rowa + (uint32_t)((ntp * 2 + vsel_l) * 16));
                mma_f16(O[2 * ntp], Pp[2 * ks][0], Pp[2 * ks][1],
                        Pp[2 * ks + 1][0], Pp[2 * ks + 1][1], b0, b1);
                mma_f16(O[2 * ntp + 1], Pp[2 * ks][0], Pp[2 * ks][1],
                        Pp[2 * ks + 1][0], Pp[2 * ks + 1][1], b2, b3);
            }
        }
        __syncthreads();
    }

    // epilogue: ctx half
    const float inv0 = 1.0f / l0, inv1 = 1.0f / l1;
    const int r0 = q0 + w * 16 + g;
#pragma unroll
    for (int nt = 0; nt < 8; nt++) {
        const int col = h * D_DIM + nt * 8 + 2 * c;
        *(uint32_t*)&ctx[((long)b * S_LEN + r0) * E_DIM + col] =
            pack_h2(O[nt][0] * inv0, O[nt][1] * inv0);
        *(uint32_t*)&ctx[((long)b * S_LEN + r0 + 8) * E_DIM + col] =
            pack_h2(O[nt][2] * inv1, O[nt][3] * inv1);
    }
}

// ---------------------------------------------------------------------------
extern "C" void kernel_launch(void* const* d_in, const int* in_sizes, int n_in,
                              void* d_out, int out_size) {
    const float* q = (const float*)d_in[0];
    const float* k = (const float*)d_in[1];
    const float* v = (const float*)d_in[2];
    const int* mask = (const int*)d_in[3];
    const float* Wq = (const float*)d_in[4];
    const float* bq = (const float*)d_in[5];
    const float* Wk = (const float*)d_in[6];
    const float* bk = (const float*)d_in[7];
    const float* Wv = (const float*)d_in[8];
    const float* bv = (const float*)d_in[9];
    const float* Wo = (const float*)d_in[10];
    const float* bo = (const float*)d_in[11];

    __half *Xh, *Wt, *Qh, *Kh, *Vh, *Ctx;
    cudaGetSymbolAddress((void**)&Xh, g_Xh);
    cudaGetSymbolAddress((void**)&Wt, g_Wt);
    cudaGetSymbolAddress((void**)&Qh, g_Qh);
    cudaGetSymbolAddress((void**)&Kh, g_Kh);
    cudaGetSymbolAddress((void**)&Vh, g_Vh);
    cudaGetSymbolAddress((void**)&Ctx, g_ctx);

    cudaFuncSetAttribute(gemm_f16<true>,
                         cudaFuncAttributeMaxDynamicSharedMemorySize, GEMM_SMEM);
    cudaFuncSetAttribute(gemm_f16<false>,
                         cudaFuncAttributeMaxDynamicSharedMemorySize, GEMM_SMEM);

    // converts
    cvt_x<<<dim3(ME / 1024, 3), 256>>>(q, k, v);
    cvt_wt<<<dim3(24, 24, 4), dim3(32, 8)>>>(Wq, Wk, Wv, Wo);

    // merged Q/K/V projections
    gemm_f16<true><<<dim3(6, 64, 3), 256, GEMM_SMEM>>>(Xh, Wt, bq, bk, bv, Qh,
                                                       Kh, Vh);

    attn_f16<<<dim3(S_LEN / 64, H_NUM, B_NUM), 128>>>(mask, Qh, Kh, Vh, Ctx);

    gemm_f16<false><<<dim3(6, 64, 1), 256, GEMM_SMEM>>>(
        Ctx, Wt + 3ll * WE, bo, bo, bo, d_out, d_out, d_out);
}